// round 9
// baseline (speedup 1.0000x reference)
#include <cuda_runtime.h>
#include <cuda_bf16.h>
#include <cstdint>

#define BATCH   64
#define CCH     512
#define HWD     196
#define NPROTO  2000
#define M_TOTAL (BATCH * HWD)   /* 12544 = 98 * 128 */
#define TILE_P  128             /* protos per CTA  (GEMM M) */
#define TILE_X  128             /* pixels per CTA  (GEMM N) */
#define KC      64              /* K chunk (channels) per stage */
#define NKC     (CCH / KC)      /* 8 chunks */
#define STAGES  3
#define EPSV    1e-4f

// ---------------- scratch (static device globals: allowed) ----------------
__device__ __nv_bfloat16 g_xT[(size_t)M_TOTAL * CCH];   // [pixel][channel] bf16
__device__ __nv_bfloat16 g_pbf[(size_t)NPROTO * CCH];   // [proto][channel] bf16
__device__ float g_x2[M_TOTAL];
__device__ float g_p2[NPROTO];

// ---------------- PTX helpers ----------------
__device__ __forceinline__ uint32_t smem_u32(const void* p) {
    uint32_t a;
    asm("{ .reg .u64 t; cvta.to.shared.u64 t, %1; cvt.u32.u64 %0, t; }" : "=r"(a) : "l"(p));
    return a;
}

__device__ __forceinline__ void cp16(uint32_t dst, const void* src, uint32_t src_bytes) {
    asm volatile("cp.async.cg.shared.global [%0], [%1], 16, %2;"
                 :: "r"(dst), "l"(src), "r"(src_bytes) : "memory");
}
__device__ __forceinline__ void cp_commit() {
    asm volatile("cp.async.commit_group;" ::: "memory");
}
template <int N> __device__ __forceinline__ void cp_wait() {
    asm volatile("cp.async.wait_group %0;" :: "n"(N) : "memory");
}

__device__ __forceinline__ void ldsm_x4(uint32_t& r0, uint32_t& r1, uint32_t& r2, uint32_t& r3,
                                        uint32_t addr) {
    asm volatile("ldmatrix.sync.aligned.m8n8.x4.shared.b16 {%0,%1,%2,%3}, [%4];"
                 : "=r"(r0), "=r"(r1), "=r"(r2), "=r"(r3) : "r"(addr));
}

__device__ __forceinline__ void mma16816(float* c, const uint32_t* a, uint32_t b0, uint32_t b1) {
    asm volatile("mma.sync.aligned.m16n8k16.row.col.f32.bf16.bf16.f32 "
                 "{%0,%1,%2,%3}, {%4,%5,%6,%7}, {%8,%9}, {%0,%1,%2,%3};"
                 : "+f"(c[0]), "+f"(c[1]), "+f"(c[2]), "+f"(c[3])
                 : "r"(a[0]), "r"(a[1]), "r"(a[2]), "r"(a[3]), "r"(b0), "r"(b1));
}

__device__ __forceinline__ uint32_t swz(uint32_t off) {   // SW128 for 128B rows
    return off ^ ((off >> 3) & 0x70);
}

// ---------------- prep kernels ----------------
__global__ void prep_proto(const float* __restrict__ proto) {
    int warp = (blockIdx.x * blockDim.x + threadIdx.x) >> 5;
    int lane = threadIdx.x & 31;
    if (warp >= NPROTO) return;
    const float* src = proto + (size_t)warp * CCH;
    __nv_bfloat16* dst = g_pbf + (size_t)warp * CCH;
    float acc = 0.f;
#pragma unroll
    for (int i = 0; i < CCH / 32; i++) {
        float v = src[lane + 32 * i];
        __nv_bfloat16 b = __float2bfloat16(v);
        float vb = __bfloat162float(b);
        acc += vb * vb;
        dst[lane + 32 * i] = b;
    }
#pragma unroll
    for (int o = 16; o; o >>= 1) acc += __shfl_xor_sync(0xffffffff, acc, o);
    if (lane == 0) g_p2[warp] = acc;
}

__global__ void prep_xT(const float* __restrict__ x) {
    __shared__ float tile[32][33];
    int b  = blockIdx.z;
    int c0 = blockIdx.y * 32;
    int h0 = blockIdx.x * 32;
    int tx = threadIdx.x, ty = threadIdx.y;   // 32 x 8
#pragma unroll
    for (int r = 0; r < 4; r++) {
        int c = c0 + ty + 8 * r;
        int h = h0 + tx;
        float v = 0.f;
        if (h < HWD) v = x[((size_t)b * CCH + c) * HWD + h];
        tile[ty + 8 * r][tx] = v;
    }
    __syncthreads();
#pragma unroll
    for (int r = 0; r < 4; r++) {
        int h = h0 + ty + 8 * r;
        if (h < HWD) {
            int m = b * HWD + h;
            g_xT[(size_t)m * CCH + c0 + tx] = __float2bfloat16(tile[tx][ty + 8 * r]);
        }
    }
}

__global__ void prep_x2() {
    int warp = (blockIdx.x * blockDim.x + threadIdx.x) >> 5;
    int lane = threadIdx.x & 31;
    if (warp >= M_TOTAL) return;
    const __nv_bfloat162* row = (const __nv_bfloat162*)(g_xT + (size_t)warp * CCH);
    float acc = 0.f;
#pragma unroll
    for (int i = 0; i < CCH / 64; i++) {
        __nv_bfloat162 v = row[lane + 32 * i];
        float a = __bfloat162float(v.x), b = __bfloat162float(v.y);
        acc += a * a + b * b;
    }
#pragma unroll
    for (int o = 16; o; o >>= 1) acc += __shfl_xor_sync(0xffffffff, acc, o);
    if (lane == 0) g_x2[warp] = acc;
}

// ---------------- main GEMM + fused epilogue ----------------
#define STAGE_BYTES (TILE_P * KC * 2 + TILE_X * KC * 2)   /* 32 KB */
#define SMEM_TOTAL  (STAGES * STAGE_BYTES)                /* 96 KB */

__global__ void __launch_bounds__(256, 2)
gemm_kernel(float* __restrict__ out) {
    extern __shared__ char smem[];
    uint32_t sb = smem_u32(smem);
    int tid = threadIdx.x;
    int lane = tid & 31;
    int w = tid >> 5;          // 8 warps
    int wm = w & 1;            // 2 along protos (64 each)
    int wn = w >> 1;           // 4 along pixels (32 each)

    int x_base = blockIdx.x * TILE_X;   // pixel tile
    int p_base = blockIdx.y * TILE_P;   // proto tile

    auto issue_loads = [&](int kc, int stage) {
        uint32_t aS = sb + stage * STAGE_BYTES;
        uint32_t bS = aS + TILE_P * KC * 2;
#pragma unroll
        for (int i = 0; i < 4; i++) {                 // A: proto rows (zfill pad)
            int lin = tid + 256 * i;
            int r = lin >> 3, q = lin & 7;
            int p = p_base + r;
            const char* src = (const char*)g_pbf + ((size_t)p * CCH + kc * KC) * 2 + q * 16;
            cp16(aS + swz(r * 128 + q * 16), src, (p < NPROTO) ? 16u : 0u);
        }
#pragma unroll
        for (int i = 0; i < 4; i++) {                 // B: pixel rows
            int lin = tid + 256 * i;
            int r = lin >> 3, q = lin & 7;
            const char* src = (const char*)g_xT + ((size_t)(x_base + r) * CCH + kc * KC) * 2 + q * 16;
            cp16(bS + swz(r * 128 + q * 16), src, 16u);
        }
        cp_commit();
    };

    issue_loads(0, 0);
    issue_loads(1, 1);

    float acc[4][4][4];
#pragma unroll
    for (int t = 0; t < 4; t++)
#pragma unroll
        for (int u = 0; u < 4; u++)
#pragma unroll
            for (int r = 0; r < 4; r++) acc[t][u][r] = 0.f;

    // Precomputed swizzled ldmatrix addresses (stage-relative).
    // s-step advances by XOR (s<<5): the s*32 bits (5..6) are disjoint from the
    // swizzle-source bits (7..9), so swz(base + s*32) == swz(base) ^ (s*32).
    // (Numerically validated in round 6 — identical rel_err.)
    uint32_t aPre[4], bPre[2];
    {
        int aRow = wm * 64 + (lane & 15);
        int aKb  = (lane >> 4) * 16;
        int bRow = wn * 32 + (lane & 7) + ((lane >> 4) << 3);
        int bKb  = ((lane >> 3) & 1) * 16;
#pragma unroll
        for (int t = 0; t < 4; t++)
            aPre[t] = swz((uint32_t)(aRow + t * 16) * 128 + aKb);
#pragma unroll
        for (int v = 0; v < 2; v++)
            bPre[v] = swz((uint32_t)(bRow + v * 16) * 128 + bKb) + TILE_P * KC * 2;
    }

    // fragment double buffers
    uint32_t af[2][4][4];
    uint32_t bf[2][2][4];

    auto load_frags = [&](uint32_t aS, int s, int buf) {
        uint32_t sx = (uint32_t)(s << 5);
#pragma unroll
        for (int t = 0; t < 4; t++)
            ldsm_x4(af[buf][t][0], af[buf][t][1], af[buf][t][2], af[buf][t][3],
                    aS + (aPre[t] ^ sx));
#pragma unroll
        for (int v = 0; v < 2; v++)
            ldsm_x4(bf[buf][v][0], bf[buf][v][1], bf[buf][v][2], bf[buf][v][3],
                    aS + (bPre[v] ^ sx));
    };

#pragma unroll 1
    for (int kc = 0; kc < NKC; kc++) {
        if (kc < NKC - 1) cp_wait<1>(); else cp_wait<0>();
        __syncthreads();

        uint32_t aS = sb + (kc % STAGES) * STAGE_BYTES;

        // critical path first: fragments for s=0
        load_frags(aS, 0, 0);
        // then the non-urgent global prefetch for kc+2 (2 stages of slack)
        if (kc + 2 < NKC) issue_loads(kc + 2, (kc + 2) % STAGES);

#pragma unroll
        for (int s = 0; s < KC / 16; s++) {
            int cur = s & 1;
            if (s < KC / 16 - 1) load_frags(aS, s + 1, cur ^ 1);
#pragma unroll
            for (int v = 0; v < 2; v++) {
#pragma unroll
                for (int t = 0; t < 4; t++) {
                    mma16816(acc[t][2 * v + 0], af[cur][t], bf[cur][v][0], bf[cur][v][1]);
                    mma16816(acc[t][2 * v + 1], af[cur][t], bf[cur][v][2], bf[cur][v][3]);
                }
            }
        }
        // no trailing __syncthreads: next iteration's barrier seals the WAR window
    }

    // --- fused epilogue from registers ---
    int g  = lane >> 2;
    int qp = (lane & 3) * 2;
#pragma unroll
    for (int u = 0; u < 4; u++) {
        int pcol = x_base + wn * 32 + u * 8 + qp;       // pixel index (even)
        int bb = pcol / HWD;
        int hw = pcol - bb * HWD;
        float x20 = __ldg(&g_x2[pcol]), x21 = __ldg(&g_x2[pcol + 1]);
        float* obb = out + (size_t)bb * NPROTO * HWD + hw;
#pragma unroll
        for (int t = 0; t < 4; t++) {
#pragma unroll
            for (int h = 0; h < 2; h++) {
                int row = p_base + wm * 64 + t * 16 + g + h * 8;   // proto
                if (row < NPROTO) {
                    float p2v = __ldg(&g_p2[row]);
                    float c0 = acc[t][u][h * 2 + 0];
                    float c1 = acc[t][u][h * 2 + 1];
                    float d0 = fmaxf(x20 - 2.0f * c0 + p2v, 0.0f);
                    float d1 = fmaxf(x21 - 2.0f * c1 + p2v, 0.0f);
                    float z0 = __fdividef(1.0f - EPSV, d0 + EPSV);
                    float z1 = __fdividef(1.0f - EPSV, d1 + EPSV);
                    float a0, a1;
                    if (z0 < 0.0625f)
                        a0 = z0 * (1.0f - z0 * (0.5f - z0 * (0.33333333f - z0 * 0.25f)));
                    else a0 = log1pf(z0);
                    if (z1 < 0.0625f)
                        a1 = z1 * (1.0f - z1 * (0.5f - z1 * (0.33333333f - z1 * 0.25f)));
                    else a1 = log1pf(z1);
                    *(float2*)(obb + (size_t)row * HWD) = make_float2(a0, a1);
                }
            }
        }
    }
}

// ---------------- launch ----------------
extern "C" void kernel_launch(void* const* d_in, const int* in_sizes, int n_in,
                              void* d_out, int out_size) {
    const float* x     = (const float*)d_in[0];
    const float* proto = (const float*)d_in[1];
    float* out = (float*)d_out;

    cudaFuncSetAttribute(gemm_kernel, cudaFuncAttributeMaxDynamicSharedMemorySize, SMEM_TOTAL);

    prep_proto<<<(NPROTO * 32 + 255) / 256, 256>>>(proto);
    prep_xT<<<dim3(7, CCH / 32, BATCH), dim3(32, 8)>>>(x);
    prep_x2<<<(M_TOTAL * 32 + 255) / 256, 256>>>();
    gemm_kernel<<<dim3(M_TOTAL / TILE_X, (NPROTO + TILE_P - 1) / TILE_P), 256, SMEM_TOTAL>>>(out);
}

// round 10
// speedup vs baseline: 1.0080x; 1.0080x over previous
#include <cuda_runtime.h>
#include <cuda_bf16.h>
#include <cstdint>

#define BATCH   64
#define CCH     512
#define HWD     196
#define NPROTO  2000
#define M_TOTAL (BATCH * HWD)   /* 12544 = 98 * 128 */
#define TILE_P  128             /* protos per CTA  (GEMM M) */
#define TILE_X  128             /* pixels per CTA  (GEMM N) */
#define KC      64              /* K chunk (channels) per stage */
#define NKC     (CCH / KC)      /* 8 chunks */
#define STAGES  3
#define EPSV    1e-4f

// ---------------- scratch (static device globals: allowed) ----------------
__device__ __nv_bfloat16 g_xT[(size_t)M_TOTAL * CCH];   // [pixel][channel] bf16
__device__ __nv_bfloat16 g_pbf[(size_t)NPROTO * CCH];   // [proto][channel] bf16
__device__ float g_x2[M_TOTAL];
__device__ float g_p2[NPROTO];

// ---------------- PTX helpers ----------------
__device__ __forceinline__ uint32_t smem_u32(const void* p) {
    uint32_t a;
    asm("{ .reg .u64 t; cvta.to.shared.u64 t, %1; cvt.u32.u64 %0, t; }" : "=r"(a) : "l"(p));
    return a;
}

__device__ __forceinline__ void cp16(uint32_t dst, const void* src, uint32_t src_bytes) {
    asm volatile("cp.async.cg.shared.global [%0], [%1], 16, %2;"
                 :: "r"(dst), "l"(src), "r"(src_bytes) : "memory");
}
__device__ __forceinline__ void cp_commit() {
    asm volatile("cp.async.commit_group;" ::: "memory");
}
template <int N> __device__ __forceinline__ void cp_wait() {
    asm volatile("cp.async.wait_group %0;" :: "n"(N) : "memory");
}

__device__ __forceinline__ void ldsm_x4(uint32_t& r0, uint32_t& r1, uint32_t& r2, uint32_t& r3,
                                        uint32_t addr) {
    asm volatile("ldmatrix.sync.aligned.m8n8.x4.shared.b16 {%0,%1,%2,%3}, [%4];"
                 : "=r"(r0), "=r"(r1), "=r"(r2), "=r"(r3) : "r"(addr));
}

__device__ __forceinline__ void mma16816(float* c, const uint32_t* a, uint32_t b0, uint32_t b1) {
    asm volatile("mma.sync.aligned.m16n8k16.row.col.f32.bf16.bf16.f32 "
                 "{%0,%1,%2,%3}, {%4,%5,%6,%7}, {%8,%9}, {%0,%1,%2,%3};"
                 : "+f"(c[0]), "+f"(c[1]), "+f"(c[2]), "+f"(c[3])
                 : "r"(a[0]), "r"(a[1]), "r"(a[2]), "r"(a[3]), "r"(b0), "r"(b1));
}

__device__ __forceinline__ uint32_t swz(uint32_t off) {   // SW128 for 128B rows
    return off ^ ((off >> 3) & 0x70);
}

// ---------------- prep kernels ----------------
__global__ void prep_proto(const float* __restrict__ proto) {
    int warp = (blockIdx.x * blockDim.x + threadIdx.x) >> 5;
    int lane = threadIdx.x & 31;
    if (warp >= NPROTO) return;
    const float* src = proto + (size_t)warp * CCH;
    __nv_bfloat16* dst = g_pbf + (size_t)warp * CCH;
    float acc = 0.f;
#pragma unroll
    for (int i = 0; i < CCH / 32; i++) {
        float v = src[lane + 32 * i];
        __nv_bfloat16 b = __float2bfloat16(v);
        float vb = __bfloat162float(b);
        acc += vb * vb;
        dst[lane + 32 * i] = b;
    }
#pragma unroll
    for (int o = 16; o; o >>= 1) acc += __shfl_xor_sync(0xffffffff, acc, o);
    if (lane == 0) g_p2[warp] = acc;
}

__global__ void prep_xT(const float* __restrict__ x) {
    __shared__ float tile[32][33];
    int b  = blockIdx.z;
    int c0 = blockIdx.y * 32;
    int h0 = blockIdx.x * 32;
    int tx = threadIdx.x, ty = threadIdx.y;   // 32 x 8
#pragma unroll
    for (int r = 0; r < 4; r++) {
        int c = c0 + ty + 8 * r;
        int h = h0 + tx;
        float v = 0.f;
        if (h < HWD) v = x[((size_t)b * CCH + c) * HWD + h];
        tile[ty + 8 * r][tx] = v;
    }
    __syncthreads();
#pragma unroll
    for (int r = 0; r < 4; r++) {
        int h = h0 + ty + 8 * r;
        if (h < HWD) {
            int m = b * HWD + h;
            g_xT[(size_t)m * CCH + c0 + tx] = __float2bfloat16(tile[tx][ty + 8 * r]);
        }
    }
}

__global__ void prep_x2() {
    int warp = (blockIdx.x * blockDim.x + threadIdx.x) >> 5;
    int lane = threadIdx.x & 31;
    if (warp >= M_TOTAL) return;
    const __nv_bfloat162* row = (const __nv_bfloat162*)(g_xT + (size_t)warp * CCH);
    float acc = 0.f;
#pragma unroll
    for (int i = 0; i < CCH / 64; i++) {
        __nv_bfloat162 v = row[lane + 32 * i];
        float a = __bfloat162float(v.x), b = __bfloat162float(v.y);
        acc += a * a + b * b;
    }
#pragma unroll
    for (int o = 16; o; o >>= 1) acc += __shfl_xor_sync(0xffffffff, acc, o);
    if (lane == 0) g_x2[warp] = acc;
}

// ---------------- main GEMM + fused epilogue ----------------
#define STAGE_BYTES (TILE_P * KC * 2 + TILE_X * KC * 2)   /* 32 KB */
#define SMEM_TOTAL  (STAGES * STAGE_BYTES)                /* 96 KB */

__global__ void __launch_bounds__(256, 2)
gemm_kernel(float* __restrict__ out) {
    extern __shared__ char smem[];
    uint32_t sb = smem_u32(smem);
    int tid = threadIdx.x;
    int lane = tid & 31;
    int w = tid >> 5;          // 8 warps
    int wm = w & 1;            // 2 along protos (64 each)
    int wn = w >> 1;           // 4 along pixels (32 each)

    int x_base = blockIdx.x * TILE_X;   // pixel tile
    int p_base = blockIdx.y * TILE_P;   // proto tile

    auto issue_loads = [&](int kc, int stage) {
        uint32_t aS = sb + stage * STAGE_BYTES;
        uint32_t bS = aS + TILE_P * KC * 2;
#pragma unroll
        for (int i = 0; i < 4; i++) {                 // A: proto rows (zfill pad)
            int lin = tid + 256 * i;
            int r = lin >> 3, q = lin & 7;
            int p = p_base + r;
            const char* src = (const char*)g_pbf + ((size_t)p * CCH + kc * KC) * 2 + q * 16;
            cp16(aS + swz(r * 128 + q * 16), src, (p < NPROTO) ? 16u : 0u);
        }
#pragma unroll
        for (int i = 0; i < 4; i++) {                 // B: pixel rows
            int lin = tid + 256 * i;
            int r = lin >> 3, q = lin & 7;
            const char* src = (const char*)g_xT + ((size_t)(x_base + r) * CCH + kc * KC) * 2 + q * 16;
            cp16(bS + swz(r * 128 + q * 16), src, 16u);
        }
        cp_commit();
    };

    issue_loads(0, 0);
    issue_loads(1, 1);

    float acc[4][4][4];
#pragma unroll
    for (int t = 0; t < 4; t++)
#pragma unroll
        for (int u = 0; u < 4; u++)
#pragma unroll
            for (int r = 0; r < 4; r++) acc[t][u][r] = 0.f;

    // Precomputed swizzled ldmatrix addresses (stage-relative).
    // s-step advances by XOR (s<<5): the s*32 bits (5..6) are disjoint from the
    // swizzle-source bits (7..9), so swz(base + s*32) == swz(base) ^ (s*32).
    // (Numerically validated in round 6 — identical rel_err.)
    uint32_t aPre[4], bPre[2];
    {
        int aRow = wm * 64 + (lane & 15);
        int aKb  = (lane >> 4) * 16;
        int bRow = wn * 32 + (lane & 7) + ((lane >> 4) << 3);
        int bKb  = ((lane >> 3) & 1) * 16;
#pragma unroll
        for (int t = 0; t < 4; t++)
            aPre[t] = swz((uint32_t)(aRow + t * 16) * 128 + aKb);
#pragma unroll
        for (int v = 0; v < 2; v++)
            bPre[v] = swz((uint32_t)(bRow + v * 16) * 128 + bKb) + TILE_P * KC * 2;
    }

    // fragment double buffers
    uint32_t af[2][4][4];
    uint32_t bf[2][2][4];

    auto load_frags = [&](uint32_t aS, int s, int buf) {
        uint32_t sx = (uint32_t)(s << 5);
#pragma unroll
        for (int t = 0; t < 4; t++)
            ldsm_x4(af[buf][t][0], af[buf][t][1], af[buf][t][2], af[buf][t][3],
                    aS + (aPre[t] ^ sx));
#pragma unroll
        for (int v = 0; v < 2; v++)
            ldsm_x4(bf[buf][v][0], bf[buf][v][1], bf[buf][v][2], bf[buf][v][3],
                    aS + (bPre[v] ^ sx));
    };

#pragma unroll 1
    for (int kc = 0; kc < NKC; kc++) {
        if (kc < NKC - 1) cp_wait<1>(); else cp_wait<0>();
        __syncthreads();

        uint32_t aS = sb + (kc % STAGES) * STAGE_BYTES;

        // critical path first: fragments for s=0
        load_frags(aS, 0, 0);
        // then the non-urgent global prefetch for kc+2 (2 stages of slack)
        if (kc + 2 < NKC) issue_loads(kc + 2, (kc + 2) % STAGES);

#pragma unroll
        for (int s = 0; s < KC / 16; s++) {
            int cur = s & 1;
            if (s < KC / 16 - 1) load_frags(aS, s + 1, cur ^ 1);
#pragma unroll
            for (int v = 0; v < 2; v++) {
#pragma unroll
                for (int t = 0; t < 4; t++) {
                    mma16816(acc[t][2 * v + 0], af[cur][t], bf[cur][v][0], bf[cur][v][1]);
                    mma16816(acc[t][2 * v + 1], af[cur][t], bf[cur][v][2], bf[cur][v][3]);
                }
            }
        }
        // no trailing __syncthreads: next iteration's barrier seals the WAR window
    }

    // --- fused epilogue from registers ---
    int g  = lane >> 2;
    int qp = (lane & 3) * 2;
#pragma unroll
    for (int u = 0; u < 4; u++) {
        int pcol = x_base + wn * 32 + u * 8 + qp;       // pixel index (even)
        int bb = pcol / HWD;
        int hw = pcol - bb * HWD;
        float x20 = __ldg(&g_x2[pcol]), x21 = __ldg(&g_x2[pcol + 1]);
        float* obb = out + (size_t)bb * NPROTO * HWD + hw;
#pragma unroll
        for (int t = 0; t < 4; t++) {
#pragma unroll
            for (int h = 0; h < 2; h++) {
                int row = p_base + wm * 64 + t * 16 + g + h * 8;   // proto
                if (row < NPROTO) {
                    float p2v = __ldg(&g_p2[row]);
                    float c0 = acc[t][u][h * 2 + 0];
                    float c1 = acc[t][u][h * 2 + 1];
                    float d0 = fmaxf(x20 - 2.0f * c0 + p2v, 0.0f);
                    float d1 = fmaxf(x21 - 2.0f * c1 + p2v, 0.0f);
                    float z0 = __fdividef(1.0f - EPSV, d0 + EPSV);
                    float z1 = __fdividef(1.0f - EPSV, d1 + EPSV);
                    float a0, a1;
                    if (z0 < 0.0625f)
                        a0 = z0 * (1.0f - z0 * (0.5f - z0 * (0.33333333f - z0 * 0.25f)));
                    else a0 = log1pf(z0);
                    if (z1 < 0.0625f)
                        a1 = z1 * (1.0f - z1 * (0.5f - z1 * (0.33333333f - z1 * 0.25f)));
                    else a1 = log1pf(z1);
                    *(float2*)(obb + (size_t)row * HWD) = make_float2(a0, a1);
                }
            }
        }
    }
}

// ---------------- launch ----------------
extern "C" void kernel_launch(void* const* d_in, const int* in_sizes, int n_in,
                              void* d_out, int out_size) {
    const float* x     = (const float*)d_in[0];
    const float* proto = (const float*)d_in[1];
    float* out = (float*)d_out;

    cudaFuncSetAttribute(gemm_kernel, cudaFuncAttributeMaxDynamicSharedMemorySize, SMEM_TOTAL);

    prep_proto<<<(NPROTO * 32 + 255) / 256, 256>>>(proto);
    prep_xT<<<dim3(7, CCH / 32, BATCH), dim3(32, 8)>>>(x);
    prep_x2<<<(M_TOTAL * 32 + 255) / 256, 256>>>();
    gemm_kernel<<<dim3(M_TOTAL / TILE_X, (NPROTO + TILE_P - 1) / TILE_P), 256, SMEM_TOTAL>>>(out);
}